// round 9
// baseline (speedup 1.0000x reference)
#include <cuda_runtime.h>
#include <cstdint>

#define N_NODES 50000
#define E_EDGES 800000
#define F       128
#define KTOP    32
#define ESTRIDE 64

// Scratch (allocation-free rule: __device__ globals)
__device__ float    g_agg[N_NODES * F];      // 25.6 MB aggregate (tf32-rounded bits)
__device__ int      g_ecnt[N_NODES];
__device__ int      g_ebuf[N_NODES * ESTRIDE];
__device__ float2   g_pack[N_NODES * KTOP];  // (deduped value, idx bits) per topk slot
__device__ uint32_t g_Wr[2 * F * F];         // tf32-rounded [Ws; Wn]

__device__ __forceinline__ uint32_t smem_u32(const void* p) {
    uint32_t a;
    asm("{ .reg .u64 t; cvta.to.shared.u64 t, %1; cvt.u32.u64 %0, t; }" : "=r"(a) : "l"(p));
    return a;
}
__device__ __forceinline__ uint32_t f2tf32(float f) {
    uint32_t u;
    asm("cvt.rna.tf32.f32 %0, %1;" : "=r"(u) : "f"(f));
    return u;
}

// ---------------------------------------------------------------------------
// prep: (a) dedup topk (last-k-wins, matches XLA scatter-set lane race) and
// pack into float2; (b) zero g_ecnt (replaces the memset node); (c) tf32-round
// W into g_Wr. No atomics here (bucket stays separate — R8 showed fusing the
// atomic section in costs ~4us of issue interference).
// ---------------------------------------------------------------------------
__global__ void prep_kernel(const float* __restrict__ vals,
                            const int* __restrict__ idxs,
                            const float* __restrict__ Ws,
                            const float* __restrict__ Wn, int n) {
    int gid = blockIdx.x * blockDim.x + threadIdx.x;
    {
        int warp = gid >> 5;
        int lane = gid & 31;
        if (warp < n) {
            int   idx = idxs[warp * KTOP + lane];
            float v   = vals[warp * KTOP + lane];
            unsigned mask = __match_any_sync(0xffffffffu, idx);
            int highest = 31 - __clz(mask);
            float keep = (lane == highest) ? v : 0.0f;
            g_pack[warp * KTOP + lane] = make_float2(keep, __int_as_float(idx));
        }
    }
    if (gid < n) g_ecnt[gid] = 0;
    if (gid < F * F) {
        g_Wr[gid]         = f2tf32(Ws[gid]);
        g_Wr[F * F + gid] = f2tf32(Wn[gid]);
    }
}

// ---------------------------------------------------------------------------
// bucket: edges grouped by dst; int2-vectorized loads (2 edges/thread).
// ---------------------------------------------------------------------------
__global__ void bucket_kernel(const int* __restrict__ src,
                              const int* __restrict__ dst, int e2) {
    int i = blockIdx.x * blockDim.x + threadIdx.x;
    if (i >= e2) return;
    int2 s = ((const int2*)src)[i];
    int2 d = ((const int2*)dst)[i];
    int p0 = atomicAdd(&g_ecnt[d.x], 1);
    if (p0 < ESTRIDE) g_ebuf[d.x * ESTRIDE + p0] = s.x;
    int p1 = atomicAdd(&g_ecnt[d.y], 1);
    if (p1 < ESTRIDE) g_ebuf[d.y * ESTRIDE + p1] = s.y;
}

// ---------------------------------------------------------------------------
// gather: one warp per dst node, 4 rotating smem accumulator rows (R7-proven:
// no cross-edge RMW hazard, MLP=4, no spills). tf32-round at writeout.
// ---------------------------------------------------------------------------
__global__ __launch_bounds__(256)
void gather_kernel(int n) {
    __shared__ float acc[8][4][F];   // 16 KB
    int warp = threadIdx.x >> 5;
    int lane = threadIdx.x & 31;
    int d = blockIdx.x * 8 + warp;
    if (d >= n) return;

    float4 z4 = make_float4(0.f, 0.f, 0.f, 0.f);
#pragma unroll
    for (int j = 0; j < 4; j++)
        *(float4*)&acc[warp][j][lane * 4] = z4;

    int cnt = g_ecnt[d];
    const int* eb = &g_ebuf[d * ESTRIDE];
    int lim = cnt < ESTRIDE ? cnt : ESTRIDE;
    int s0 = (lane      < lim) ? eb[lane]      : 0;
    int s1 = (lane + 32 < lim) ? eb[lane + 32] : 0;

    float2 pcur[4];
#pragma unroll
    for (int j = 0; j < 4; j++) {
        if (j < lim) {
            int s = __shfl_sync(0xffffffffu, s0, j);
            pcur[j] = g_pack[(size_t)s * KTOP + lane];
        } else pcur[j] = make_float2(0.f, 0.f);
    }

    for (int i = 0; i < lim; i += 4) {
        float2 pnext[4];
#pragma unroll
        for (int j = 0; j < 4; j++) {
            int ei = i + 4 + j;
            if (ei < lim) {
                int s = __shfl_sync(0xffffffffu, (ei < 32) ? s0 : s1, ei & 31);
                pnext[j] = g_pack[(size_t)s * KTOP + lane];
            } else pnext[j] = make_float2(0.f, 0.f);
        }
#pragma unroll
        for (int j = 0; j < 4; j++) {
            if (pcur[j].x != 0.0f) {
                int c = __float_as_int(pcur[j].y);
                acc[warp][j][c] += pcur[j].x;
            }
        }
#pragma unroll
        for (int j = 0; j < 4; j++) pcur[j] = pnext[j];
    }
    __syncwarp();

    float w = 1.0f / (float)(cnt > 0 ? cnt : 1);
    float4 a0 = *(float4*)&acc[warp][0][lane * 4];
    float4 a1 = *(float4*)&acc[warp][1][lane * 4];
    float4 a2 = *(float4*)&acc[warp][2][lane * 4];
    float4 a3 = *(float4*)&acc[warp][3][lane * 4];
    uint4 o;
    o.x = f2tf32((a0.x + a1.x + a2.x + a3.x) * w);
    o.y = f2tf32((a0.y + a1.y + a2.y + a3.y) * w);
    o.z = f2tf32((a0.z + a1.z + a2.z + a3.z) * w);
    o.w = f2tf32((a0.w + a1.w + a2.w + a3.w) * w);
    *(uint4*)&g_agg[(size_t)d * F + lane * 4] = o;
}

// ---------------------------------------------------------------------------
// Half-GEMM (K=128), 2-stage cp.async, 128x128 tile, 8 warps, m16n8k8 tf32.
//   NEIGH=0: out = feat @ Wr[0..] + bias          (A raw f32 bits, truncated)
//   NEIGH=1: out = out + g_agg @ Wr[F*F..]        (A pre-rounded bits)
// ---------------------------------------------------------------------------
#define SA_STRIDE 36
#define SB_STRIDE 136
#define SA_BUF (128 * SA_STRIDE)
#define SB_BUF (32 * SB_STRIDE)
#define SMEM_BYTES ((2 * SA_BUF + 2 * SB_BUF) * 4)   // 71680 B

__device__ __forceinline__ void cp16(uint32_t saddr, const void* g, int pbytes) {
    asm volatile("cp.async.ca.shared.global [%0], [%1], 16, %2;"
                 :: "r"(saddr), "l"(g), "r"(pbytes));
}
__device__ __forceinline__ void mma_tf32(float* d, const uint32_t* a, const uint32_t* b) {
    asm volatile("mma.sync.aligned.m16n8k8.row.col.f32.tf32.tf32.f32 "
                 "{%0,%1,%2,%3}, {%4,%5,%6,%7}, {%8,%9}, {%0,%1,%2,%3};"
                 : "+f"(d[0]), "+f"(d[1]), "+f"(d[2]), "+f"(d[3])
                 : "r"(a[0]), "r"(a[1]), "r"(a[2]), "r"(a[3]),
                   "r"(b[0]), "r"(b[1]));
}

template <bool NEIGH>
__global__ __launch_bounds__(256, 2)
void gemm_half_kernel(const float* __restrict__ feat,
                      const float* __restrict__ bias,
                      float* __restrict__ out, int n) {
    extern __shared__ uint32_t dsm[];
    uint32_t* sA = dsm;
    uint32_t* sB = dsm + 2 * SA_BUF;
    uint32_t sA_addr = smem_u32(sA);
    uint32_t sB_addr = smem_u32(sB);

    int tid    = threadIdx.x;
    int wid    = tid >> 5;
    int lane   = tid & 31;
    int warp_m = wid & 1;
    int warp_n = wid >> 1;
    int r0     = blockIdx.x * 128;
    int qr     = lane >> 2;
    int qc     = lane & 3;

    const float* Asrc = NEIGH ? g_agg : feat;
    const uint32_t* Bsrc = g_Wr + (NEIGH ? F * F : 0);

    int a_row[4], a_q[4], b_k[4], b_q[4];
#pragma unroll
    for (int l = 0; l < 4; l++) {
        int idx = tid + l * 256;
        a_row[l] = idx >> 3;  a_q[l] = idx & 7;
        b_k[l]   = idx >> 5;  b_q[l] = idx & 31;
    }

    float acc[4][4][4];
#pragma unroll
    for (int mt = 0; mt < 4; mt++)
#pragma unroll
        for (int nt = 0; nt < 4; nt++)
#pragma unroll
            for (int r = 0; r < 4; r++) acc[mt][nt][r] = 0.0f;

    auto issue_chunk = [&](int c, int buf) {
        int kq = c * 32;
#pragma unroll
        for (int l = 0; l < 4; l++) {
            int grow = r0 + a_row[l];
            int pb = (grow < n) ? 16 : 0;
            const float* g = &Asrc[(size_t)(grow < n ? grow : 0) * F + kq + a_q[l] * 4];
            cp16(sA_addr + (buf * SA_BUF + a_row[l] * SA_STRIDE + a_q[l] * 4) * 4, g, pb);
        }
#pragma unroll
        for (int l = 0; l < 4; l++) {
            const uint32_t* g = &Bsrc[(size_t)(kq + b_k[l]) * F + b_q[l] * 4];
            cp16(sB_addr + (buf * SB_BUF + b_k[l] * SB_STRIDE + b_q[l] * 4) * 4, g, 16);
        }
        asm volatile("cp.async.commit_group;" ::: "memory");
    };

    issue_chunk(0, 0);

    for (int c = 0; c < 4; c++) {
        int buf = c & 1;
        if (c < 3) {
            issue_chunk(c + 1, buf ^ 1);
            asm volatile("cp.async.wait_group 1;" ::: "memory");
        } else {
            asm volatile("cp.async.wait_group 0;" ::: "memory");
        }
        __syncthreads();

        const uint32_t* cA = &sA[buf * SA_BUF];
        const uint32_t* cB = &sB[buf * SB_BUF];
#pragma unroll
        for (int ks = 0; ks < 4; ks++) {
            int k8 = ks * 8;
            uint32_t a[4][4];
#pragma unroll
            for (int mt = 0; mt < 4; mt++) {
                int mrow = warp_m * 64 + mt * 16;
                a[mt][0] = cA[(mrow + qr    ) * SA_STRIDE + k8 + qc    ];
                a[mt][1] = cA[(mrow + qr + 8) * SA_STRIDE + k8 + qc    ];
                a[mt][2] = cA[(mrow + qr    ) * SA_STRIDE + k8 + qc + 4];
                a[mt][3] = cA[(mrow + qr + 8) * SA_STRIDE + k8 + qc + 4];
            }
            uint32_t b[4][2];
#pragma unroll
            for (int nt = 0; nt < 4; nt++) {
                int ncol = warp_n * 32 + nt * 8;
                b[nt][0] = cB[(k8 + qc    ) * SB_STRIDE + ncol + qr];
                b[nt][1] = cB[(k8 + qc + 4) * SB_STRIDE + ncol + qr];
            }
#pragma unroll
            for (int mt = 0; mt < 4; mt++)
#pragma unroll
                for (int nt = 0; nt < 4; nt++)
                    mma_tf32(acc[mt][nt], a[mt], b[nt]);
        }
        __syncthreads();
    }

    // Epilogue
#pragma unroll
    for (int mt = 0; mt < 4; mt++) {
        int row0 = r0 + warp_m * 64 + mt * 16 + qr;
#pragma unroll
        for (int nt = 0; nt < 4; nt++) {
            int col = warp_n * 32 + nt * 8 + qc * 2;
            float b0, b1;
            if (NEIGH) { b0 = 0.f; b1 = 0.f; }
            else { b0 = __ldg(&bias[col]); b1 = __ldg(&bias[col + 1]); }
            if (row0 < n) {
                float2 prev = NEIGH ? *(const float2*)&out[(size_t)row0 * F + col]
                                    : make_float2(0.f, 0.f);
                float2 o = make_float2(acc[mt][nt][0] + b0 + prev.x,
                                       acc[mt][nt][1] + b1 + prev.y);
                *(float2*)&out[(size_t)row0 * F + col] = o;
            }
            if (row0 + 8 < n) {
                float2 prev = NEIGH ? *(const float2*)&out[(size_t)(row0 + 8) * F + col]
                                    : make_float2(0.f, 0.f);
                float2 o = make_float2(acc[mt][nt][2] + b0 + prev.x,
                                       acc[mt][nt][3] + b1 + prev.y);
                *(float2*)&out[(size_t)(row0 + 8) * F + col] = o;
            }
        }
    }
}

// ---------------------------------------------------------------------------
// Launch: fork-join capture graph.
//   main: prep -> [fork] bucket -> gather -> [join] -> gemm_neigh
//   side:          gemm_self (feat @ Ws + b), hidden under bucket+gather
// ---------------------------------------------------------------------------
extern "C" void kernel_launch(void* const* d_in, const int* in_sizes, int n_in,
                              void* d_out, int out_size) {
    const float* feat = (const float*)d_in[0];
    const float* tkv  = (const float*)d_in[1];
    const int*   tki  = (const int*)  d_in[2];
    const int*   src  = (const int*)  d_in[3];
    const int*   dst  = (const int*)  d_in[4];
    const float* Ws   = (const float*)d_in[5];
    const float* bs   = (const float*)d_in[6];
    const float* Wn   = (const float*)d_in[7];
    float* out = (float*)d_out;

    const int n = N_NODES;
    const int e = E_EDGES;

    static cudaStream_t s2 = nullptr;
    static cudaEvent_t evFork = nullptr, evJoin = nullptr;
    if (!s2) {
        cudaStreamCreateWithFlags(&s2, cudaStreamNonBlocking);
        cudaEventCreateWithFlags(&evFork, cudaEventDisableTiming);
        cudaEventCreateWithFlags(&evJoin, cudaEventDisableTiming);
        cudaFuncSetAttribute(gemm_half_kernel<false>,
                             cudaFuncAttributeMaxDynamicSharedMemorySize, SMEM_BYTES);
        cudaFuncSetAttribute(gemm_half_kernel<true>,
                             cudaFuncAttributeMaxDynamicSharedMemorySize, SMEM_BYTES);
    }

    prep_kernel<<<(n * 32 + 255) / 256, 256>>>(tkv, tki, Ws, Wn, n);

    // fork: self-GEMM on side stream (depends only on prep's g_Wr)
    cudaEventRecord(evFork, 0);
    cudaStreamWaitEvent(s2, evFork, 0);
    gemm_half_kernel<false><<<(n + 127) / 128, 256, SMEM_BYTES, s2>>>(feat, bs, out, n);
    cudaEventRecord(evJoin, s2);

    // main: sparse path
    bucket_kernel<<<(e / 2 + 255) / 256, 256>>>(src, dst, e / 2);
    gather_kernel<<<(n + 7) / 8, 256>>>(n);

    // join, then neighbor-GEMM accumulates into out
    cudaStreamWaitEvent(0, evJoin, 0);
    gemm_half_kernel<true><<<(n + 127) / 128, 256, SMEM_BYTES>>>(feat, bs, out, n);
}

// round 10
// speedup vs baseline: 1.6911x; 1.6911x over previous
#include <cuda_runtime.h>
#include <cstdint>

#define N_NODES 50000
#define E_EDGES 800000
#define F       128
#define KTOP    32
#define ESTRIDE 64

// Scratch (allocation-free rule: __device__ globals)
__device__ float    g_agg[N_NODES * F];      // 25.6 MB aggregate (tf32-rounded bits)
__device__ int      g_ecnt[N_NODES];
__device__ int      g_ebuf[N_NODES * ESTRIDE];
__device__ float2   g_pack[N_NODES * KTOP];  // (deduped value, idx bits) per topk slot
__device__ uint32_t g_Wr[2 * F * F];         // tf32-rounded [Ws; Wn]

__device__ __forceinline__ uint32_t smem_u32(const void* p) {
    uint32_t a;
    asm("{ .reg .u64 t; cvta.to.shared.u64 t, %1; cvt.u32.u64 %0, t; }" : "=r"(a) : "l"(p));
    return a;
}
__device__ __forceinline__ uint32_t f2tf32(float f) {
    uint32_t u;
    asm("cvt.rna.tf32.f32 %0, %1;" : "=r"(u) : "f"(f));
    return u;
}

// ---------------------------------------------------------------------------
// prep: (a) dedup topk (last-k-wins, matches XLA scatter-set lane race) and
// pack into float2; (b) zero g_ecnt (replaces memset node); (c) tf32-round W.
// ---------------------------------------------------------------------------
__global__ void prep_kernel(const float* __restrict__ vals,
                            const int* __restrict__ idxs,
                            const float* __restrict__ Ws,
                            const float* __restrict__ Wn, int n) {
    int gid = blockIdx.x * blockDim.x + threadIdx.x;
    {
        int warp = gid >> 5;
        int lane = gid & 31;
        if (warp < n) {
            int   idx = idxs[warp * KTOP + lane];
            float v   = vals[warp * KTOP + lane];
            unsigned mask = __match_any_sync(0xffffffffu, idx);
            int highest = 31 - __clz(mask);
            float keep = (lane == highest) ? v : 0.0f;
            g_pack[warp * KTOP + lane] = make_float2(keep, __int_as_float(idx));
        }
    }
    if (gid < n) g_ecnt[gid] = 0;
    if (gid < F * F) {
        g_Wr[gid]         = f2tf32(Ws[gid]);
        g_Wr[F * F + gid] = f2tf32(Wn[gid]);
    }
}

// ---------------------------------------------------------------------------
// bucket: edges grouped by dst; int2-vectorized loads (2 edges/thread).
// ---------------------------------------------------------------------------
__global__ void bucket_kernel(const int* __restrict__ src,
                              const int* __restrict__ dst, int e2) {
    int i = blockIdx.x * blockDim.x + threadIdx.x;
    if (i >= e2) return;
    int2 s = ((const int2*)src)[i];
    int2 d = ((const int2*)dst)[i];
    int p0 = atomicAdd(&g_ecnt[d.x], 1);
    if (p0 < ESTRIDE) g_ebuf[d.x * ESTRIDE + p0] = s.x;
    int p1 = atomicAdd(&g_ecnt[d.y], 1);
    if (p1 < ESTRIDE) g_ebuf[d.y * ESTRIDE + p1] = s.y;
}

// ---------------------------------------------------------------------------
// gather: one warp per dst node, 4 rotating smem accumulator rows (R7-proven:
// cross-edge RMWs disjoint, within-edge columns distinct after dedup, MLP=4).
// tf32-round at writeout so the GEMM's A-side truncation of agg is exact.
// ---------------------------------------------------------------------------
__global__ __launch_bounds__(256)
void gather_kernel(int n) {
    __shared__ float acc[8][4][F];   // 16 KB
    int warp = threadIdx.x >> 5;
    int lane = threadIdx.x & 31;
    int d = blockIdx.x * 8 + warp;
    if (d >= n) return;

    float4 z4 = make_float4(0.f, 0.f, 0.f, 0.f);
#pragma unroll
    for (int j = 0; j < 4; j++)
        *(float4*)&acc[warp][j][lane * 4] = z4;

    int cnt = g_ecnt[d];
    const int* eb = &g_ebuf[d * ESTRIDE];
    int lim = cnt < ESTRIDE ? cnt : ESTRIDE;
    int s0 = (lane      < lim) ? eb[lane]      : 0;
    int s1 = (lane + 32 < lim) ? eb[lane + 32] : 0;

    float2 pcur[4];
#pragma unroll
    for (int j = 0; j < 4; j++) {
        if (j < lim) {
            int s = __shfl_sync(0xffffffffu, s0, j);
            pcur[j] = g_pack[(size_t)s * KTOP + lane];
        } else pcur[j] = make_float2(0.f, 0.f);
    }

    for (int i = 0; i < lim; i += 4) {
        float2 pnext[4];
#pragma unroll
        for (int j = 0; j < 4; j++) {
            int ei = i + 4 + j;
            if (ei < lim) {
                int s = __shfl_sync(0xffffffffu, (ei < 32) ? s0 : s1, ei & 31);
                pnext[j] = g_pack[(size_t)s * KTOP + lane];
            } else pnext[j] = make_float2(0.f, 0.f);
        }
#pragma unroll
        for (int j = 0; j < 4; j++) {
            if (pcur[j].x != 0.0f) {
                int c = __float_as_int(pcur[j].y);
                acc[warp][j][c] += pcur[j].x;
            }
        }
#pragma unroll
        for (int j = 0; j < 4; j++) pcur[j] = pnext[j];
    }
    __syncwarp();

    float w = 1.0f / (float)(cnt > 0 ? cnt : 1);
    float4 a0 = *(float4*)&acc[warp][0][lane * 4];
    float4 a1 = *(float4*)&acc[warp][1][lane * 4];
    float4 a2 = *(float4*)&acc[warp][2][lane * 4];
    float4 a3 = *(float4*)&acc[warp][3][lane * 4];
    uint4 o;
    o.x = f2tf32((a0.x + a1.x + a2.x + a3.x) * w);
    o.y = f2tf32((a0.y + a1.y + a2.y + a3.y) * w);
    o.z = f2tf32((a0.z + a1.z + a2.z + a3.z) * w);
    o.w = f2tf32((a0.w + a1.w + a2.w + a3.w) * w);
    *(uint4*)&g_agg[(size_t)d * F + lane * 4] = o;
}

// ---------------------------------------------------------------------------
// tf32 mma.sync fused GEMM, 2-stage cp.async (R7-proven):
//   out[M,128] = [feat|agg][M,256] @ g_Wr + bias
// CTA: 128x128 tile, 8 warps (2x4), warp tile 64x32, m16n8k8 HMMA.
// A-side raw f32 bits (feat truncated; agg pre-rounded), B-side pre-rounded.
// ---------------------------------------------------------------------------
#define SA_STRIDE 36
#define SB_STRIDE 136
#define SA_BUF (128 * SA_STRIDE)
#define SB_BUF (32 * SB_STRIDE)
#define SMEM_BYTES ((2 * SA_BUF + 2 * SB_BUF) * 4)   // 71680 B

__device__ __forceinline__ void cp16(uint32_t saddr, const void* g, int pbytes) {
    asm volatile("cp.async.ca.shared.global [%0], [%1], 16, %2;"
                 :: "r"(saddr), "l"(g), "r"(pbytes));
}
__device__ __forceinline__ void mma_tf32(float* d, const uint32_t* a, const uint32_t* b) {
    asm volatile("mma.sync.aligned.m16n8k8.row.col.f32.tf32.tf32.f32 "
                 "{%0,%1,%2,%3}, {%4,%5,%6,%7}, {%8,%9}, {%0,%1,%2,%3};"
                 : "+f"(d[0]), "+f"(d[1]), "+f"(d[2]), "+f"(d[3])
                 : "r"(a[0]), "r"(a[1]), "r"(a[2]), "r"(a[3]),
                   "r"(b[0]), "r"(b[1]));
}

__global__ __launch_bounds__(256, 2)
void gemm_mma_kernel(const float* __restrict__ feat,
                     const float* __restrict__ bias,
                     float* __restrict__ out, int n) {
    extern __shared__ uint32_t dsm[];
    uint32_t* sA = dsm;                 // [2][SA_BUF]
    uint32_t* sB = dsm + 2 * SA_BUF;    // [2][SB_BUF]
    uint32_t sA_addr = smem_u32(sA);
    uint32_t sB_addr = smem_u32(sB);

    int tid    = threadIdx.x;
    int wid    = tid >> 5;
    int lane   = tid & 31;
    int warp_m = wid & 1;
    int warp_n = wid >> 1;
    int r0     = blockIdx.x * 128;
    int qr     = lane >> 2;
    int qc     = lane & 3;

    int a_row[4], a_q[4], b_k[4], b_q[4];
#pragma unroll
    for (int l = 0; l < 4; l++) {
        int idx = tid + l * 256;
        a_row[l] = idx >> 3;  a_q[l] = idx & 7;
        b_k[l]   = idx >> 5;  b_q[l] = idx & 31;
    }

    float acc[4][4][4];
#pragma unroll
    for (int mt = 0; mt < 4; mt++)
#pragma unroll
        for (int nt = 0; nt < 4; nt++)
#pragma unroll
            for (int r = 0; r < 4; r++) acc[mt][nt][r] = 0.0f;

    auto issue_chunk = [&](int c, int buf) {
        const float* Asrc = (c < 4) ? feat : g_agg;
        const uint32_t* Bsrc = g_Wr + (c < 4 ? 0 : F * F);
        int kq = (c & 3) * 32;
#pragma unroll
        for (int l = 0; l < 4; l++) {
            int grow = r0 + a_row[l];
            int pb = (grow < n) ? 16 : 0;
            const float* g = &Asrc[(size_t)(grow < n ? grow : 0) * F + kq + a_q[l] * 4];
            cp16(sA_addr + (buf * SA_BUF + a_row[l] * SA_STRIDE + a_q[l] * 4) * 4, g, pb);
        }
#pragma unroll
        for (int l = 0; l < 4; l++) {
            const uint32_t* g = &Bsrc[(size_t)(kq + b_k[l]) * F + b_q[l] * 4];
            cp16(sB_addr + (buf * SB_BUF + b_k[l] * SB_STRIDE + b_q[l] * 4) * 4, g, 16);
        }
        asm volatile("cp.async.commit_group;" ::: "memory");
    };

    issue_chunk(0, 0);

    for (int c = 0; c < 8; c++) {
        int buf = c & 1;
        if (c < 7) {
            issue_chunk(c + 1, buf ^ 1);
            asm volatile("cp.async.wait_group 1;" ::: "memory");
        } else {
            asm volatile("cp.async.wait_group 0;" ::: "memory");
        }
        __syncthreads();

        const uint32_t* cA = &sA[buf * SA_BUF];
        const uint32_t* cB = &sB[buf * SB_BUF];
#pragma unroll
        for (int ks = 0; ks < 4; ks++) {
            int k8 = ks * 8;
            uint32_t a[4][4];
#pragma unroll
            for (int mt = 0; mt < 4; mt++) {
                int mrow = warp_m * 64 + mt * 16;
                a[mt][0] = cA[(mrow + qr    ) * SA_STRIDE + k8 + qc    ];
                a[mt][1] = cA[(mrow + qr + 8) * SA_STRIDE + k8 + qc    ];
                a[mt][2] = cA[(mrow + qr    ) * SA_STRIDE + k8 + qc + 4];
                a[mt][3] = cA[(mrow + qr + 8) * SA_STRIDE + k8 + qc + 4];
            }
            uint32_t b[4][2];
#pragma unroll
            for (int nt = 0; nt < 4; nt++) {
                int ncol = warp_n * 32 + nt * 8;
                b[nt][0] = cB[(k8 + qc    ) * SB_STRIDE + ncol + qr];
                b[nt][1] = cB[(k8 + qc + 4) * SB_STRIDE + ncol + qr];
            }
#pragma unroll
            for (int mt = 0; mt < 4; mt++)
#pragma unroll
                for (int nt = 0; nt < 4; nt++)
                    mma_tf32(acc[mt][nt], a[mt], b[nt]);
        }
        __syncthreads();
    }

    // Epilogue: c0/c1 @ (row qr, col 2qc/2qc+1), c2/c3 @ row qr+8
#pragma unroll
    for (int mt = 0; mt < 4; mt++) {
        int row0 = r0 + warp_m * 64 + mt * 16 + qr;
#pragma unroll
        for (int nt = 0; nt < 4; nt++) {
            int col = warp_n * 32 + nt * 8 + qc * 2;
            float b0 = __ldg(&bias[col]);
            float b1 = __ldg(&bias[col + 1]);
            if (row0 < n) {
                float2 o = make_float2(acc[mt][nt][0] + b0, acc[mt][nt][1] + b1);
                *(float2*)&out[(size_t)row0 * F + col] = o;
            }
            if (row0 + 8 < n) {
                float2 o = make_float2(acc[mt][nt][2] + b0, acc[mt][nt][3] + b1);
                *(float2*)&out[(size_t)(row0 + 8) * F + col] = o;
            }
        }
    }
}

// ---------------------------------------------------------------------------
// Launch: single stream, 4 kernels: prep -> bucket -> gather -> gemm
// ---------------------------------------------------------------------------
extern "C" void kernel_launch(void* const* d_in, const int* in_sizes, int n_in,
                              void* d_out, int out_size) {
    const float* feat = (const float*)d_in[0];
    const float* tkv  = (const float*)d_in[1];
    const int*   tki  = (const int*)  d_in[2];
    const int*   src  = (const int*)  d_in[3];
    const int*   dst  = (const int*)  d_in[4];
    const float* Ws   = (const float*)d_in[5];
    const float* bs   = (const float*)d_in[6];
    const float* Wn   = (const float*)d_in[7];
    float* out = (float*)d_out;

    const int n = N_NODES;
    const int e = E_EDGES;

    cudaFuncSetAttribute(gemm_mma_kernel,
                         cudaFuncAttributeMaxDynamicSharedMemorySize, SMEM_BYTES);

    prep_kernel<<<(n * 32 + 255) / 256, 256>>>(tkv, tki, Ws, Wn, n);
    bucket_kernel<<<(e / 2 + 255) / 256, 256>>>(src, dst, e / 2);
    gather_kernel<<<(n + 7) / 8, 256>>>(n);
    gemm_mma_kernel<<<(n + 127) / 128, 256, SMEM_BYTES>>>(feat, bs, out, n);
}

// round 11
// speedup vs baseline: 1.6977x; 1.0039x over previous
#include <cuda_runtime.h>
#include <cstdint>

#define N_NODES 50000
#define E_EDGES 800000
#define F       128
#define KTOP    32
#define ESTRIDE 64

// Scratch (allocation-free rule: __device__ globals)
__device__ float    g_agg[N_NODES * F];      // 25.6 MB aggregate (tf32-rounded bits)
__device__ int      g_ecnt[N_NODES];
__device__ int      g_ebuf[N_NODES * ESTRIDE];
__device__ uint32_t g_pack[N_NODES * KTOP];  // (val & ~0x7F) | idx, 12.8 MB
__device__ uint32_t g_Wr[2 * F * F];         // tf32-rounded [Ws; Wn]

__device__ __forceinline__ uint32_t smem_u32(const void* p) {
    uint32_t a;
    asm("{ .reg .u64 t; cvta.to.shared.u64 t, %1; cvt.u32.u64 %0, t; }" : "=r"(a) : "l"(p));
    return a;
}
__device__ __forceinline__ uint32_t f2tf32(float f) {
    uint32_t u;
    asm("cvt.rna.tf32.f32 %0, %1;" : "=r"(u) : "f"(f));
    return u;
}

// ---------------------------------------------------------------------------
// prep: (a) dedup topk (last-k-wins, matches XLA scatter-set lane race) and
// pack (value's top 25 bits | 7-bit column idx) into ONE uint32 per slot —
// the clobbered low mantissa bits cost <=1.5e-5 relative, far below the tf32
// noise floor; (b) zero g_ecnt; (c) tf32-round W.
// ---------------------------------------------------------------------------
__global__ void prep_kernel(const float* __restrict__ vals,
                            const int* __restrict__ idxs,
                            const float* __restrict__ Ws,
                            const float* __restrict__ Wn, int n) {
    int gid = blockIdx.x * blockDim.x + threadIdx.x;
    {
        int warp = gid >> 5;
        int lane = gid & 31;
        if (warp < n) {
            int   idx = idxs[warp * KTOP + lane];
            float v   = vals[warp * KTOP + lane];
            unsigned mask = __match_any_sync(0xffffffffu, idx);
            int highest = 31 - __clz(mask);
            float keep = (lane == highest) ? v : 0.0f;
            g_pack[warp * KTOP + lane] =
                (__float_as_uint(keep) & ~0x7Fu) | (uint32_t)idx;
        }
    }
    if (gid < n) g_ecnt[gid] = 0;
    if (gid < F * F) {
        g_Wr[gid]         = f2tf32(Ws[gid]);
        g_Wr[F * F + gid] = f2tf32(Wn[gid]);
    }
}

// ---------------------------------------------------------------------------
// bucket: edges grouped by dst; int4-vectorized loads (4 edges/thread).
// ---------------------------------------------------------------------------
__global__ void bucket_kernel(const int* __restrict__ src,
                              const int* __restrict__ dst, int e4) {
    int i = blockIdx.x * blockDim.x + threadIdx.x;
    if (i >= e4) return;
    int4 s = ((const int4*)src)[i];
    int4 d = ((const int4*)dst)[i];
    int p;
    p = atomicAdd(&g_ecnt[d.x], 1); if (p < ESTRIDE) g_ebuf[d.x * ESTRIDE + p] = s.x;
    p = atomicAdd(&g_ecnt[d.y], 1); if (p < ESTRIDE) g_ebuf[d.y * ESTRIDE + p] = s.y;
    p = atomicAdd(&g_ecnt[d.z], 1); if (p < ESTRIDE) g_ebuf[d.z * ESTRIDE + p] = s.z;
    p = atomicAdd(&g_ecnt[d.w], 1); if (p < ESTRIDE) g_ebuf[d.w * ESTRIDE + p] = s.w;
}

// ---------------------------------------------------------------------------
// gather: one warp per dst node, 4 rotating smem accumulator rows (cross-edge
// RMWs disjoint; within-edge columns distinct after dedup; MLP=4). One packed
// LDG.32 per lane per edge (half of R10's stream). The packed word is used
// directly as the addend — its low-7-bit idx pollution is <=2^-16 relative.
// tf32-round at writeout so the GEMM's A-side truncation of agg is exact.
// ---------------------------------------------------------------------------
__global__ __launch_bounds__(256)
void gather_kernel(int n) {
    __shared__ float acc[8][4][F];   // 16 KB
    int warp = threadIdx.x >> 5;
    int lane = threadIdx.x & 31;
    int d = blockIdx.x * 8 + warp;
    if (d >= n) return;

    float4 z4 = make_float4(0.f, 0.f, 0.f, 0.f);
#pragma unroll
    for (int j = 0; j < 4; j++)
        *(float4*)&acc[warp][j][lane * 4] = z4;

    int cnt = g_ecnt[d];
    const int* eb = &g_ebuf[d * ESTRIDE];
    int lim = cnt < ESTRIDE ? cnt : ESTRIDE;
    int s0 = (lane      < lim) ? eb[lane]      : 0;
    int s1 = (lane + 32 < lim) ? eb[lane + 32] : 0;

    uint32_t pcur[4];
#pragma unroll
    for (int j = 0; j < 4; j++) {
        if (j < lim) {
            int s = __shfl_sync(0xffffffffu, s0, j);
            pcur[j] = g_pack[(size_t)s * KTOP + lane];
        } else pcur[j] = 0u;
    }

    for (int i = 0; i < lim; i += 4) {
        uint32_t pnext[4];
#pragma unroll
        for (int j = 0; j < 4; j++) {
            int ei = i + 4 + j;
            if (ei < lim) {
                int s = __shfl_sync(0xffffffffu, (ei < 32) ? s0 : s1, ei & 31);
                pnext[j] = g_pack[(size_t)s * KTOP + lane];
            } else pnext[j] = 0u;
        }
#pragma unroll
        for (int j = 0; j < 4; j++) {
            if (pcur[j] & ~0x7Fu) {              // value bits nonzero
                int c = pcur[j] & 0x7Fu;
                acc[warp][j][c] += __uint_as_float(pcur[j]);
            }
        }
#pragma unroll
        for (int j = 0; j < 4; j++) pcur[j] = pnext[j];
    }
    __syncwarp();

    float w = 1.0f / (float)(cnt > 0 ? cnt : 1);
    float4 a0 = *(float4*)&acc[warp][0][lane * 4];
    float4 a1 = *(float4*)&acc[warp][1][lane * 4];
    float4 a2 = *(float4*)&acc[warp][2][lane * 4];
    float4 a3 = *(float4*)&acc[warp][3][lane * 4];
    uint4 o;
    o.x = f2tf32((a0.x + a1.x + a2.x + a3.x) * w);
    o.y = f2tf32((a0.y + a1.y + a2.y + a3.y) * w);
    o.z = f2tf32((a0.z + a1.z + a2.z + a3.z) * w);
    o.w = f2tf32((a0.w + a1.w + a2.w + a3.w) * w);
    *(uint4*)&g_agg[(size_t)d * F + lane * 4] = o;
}

// ---------------------------------------------------------------------------
// tf32 mma.sync fused GEMM, 2-stage cp.async (unchanged from R10 champion):
//   out[M,128] = [feat|agg][M,256] @ g_Wr + bias
// ---------------------------------------------------------------------------
#define SA_STRIDE 36
#define SB_STRIDE 136
#define SA_BUF (128 * SA_STRIDE)
#define SB_BUF (32 * SB_STRIDE)
#define SMEM_BYTES ((2 * SA_BUF + 2 * SB_BUF) * 4)   // 71680 B

__device__ __forceinline__ void cp16(uint32_t saddr, const void* g, int pbytes) {
    asm volatile("cp.async.ca.shared.global [%0], [%1], 16, %2;"
                 :: "r"(saddr), "l"(g), "r"(pbytes));
}
__device__ __forceinline__ void mma_tf32(float* d, const uint32_t* a, const uint32_t* b) {
    asm volatile("mma.sync.aligned.m16n8k8.row.col.f32.tf32.tf32.f32 "
                 "{%0,%1,%2,%3}, {%4,%5,%6,%7}, {%8,%9}, {%0,%1,%2,%3};"
                 : "+f"(d[0]), "+f"(d[1]), "+f"(d[2]), "+f"(d[3])
                 : "r"(a[0]), "r"(a[1]), "r"(a[2]), "r"(a[3]),
                   "r"(b[0]), "r"(b[1]));
}

__global__ __launch_bounds__(256, 2)
void gemm_mma_kernel(const float* __restrict__ feat,
                     const float* __restrict__ bias,
                     float* __restrict__ out, int n) {
    extern __shared__ uint32_t dsm[];
    uint32_t* sA = dsm;
    uint32_t* sB = dsm + 2 * SA_BUF;
    uint32_t sA_addr = smem_u32(sA);
    uint32_t sB_addr = smem_u32(sB);

    int tid    = threadIdx.x;
    int wid    = tid >> 5;
    int lane   = tid & 31;
    int warp_m = wid & 1;
    int warp_n = wid >> 1;
    int r0     = blockIdx.x * 128;
    int qr     = lane >> 2;
    int qc     = lane & 3;

    int a_row[4], a_q[4], b_k[4], b_q[4];
#pragma unroll
    for (int l = 0; l < 4; l++) {
        int idx = tid + l * 256;
        a_row[l] = idx >> 3;  a_q[l] = idx & 7;
        b_k[l]   = idx >> 5;  b_q[l] = idx & 31;
    }

    float acc[4][4][4];
#pragma unroll
    for (int mt = 0; mt < 4; mt++)
#pragma unroll
        for (int nt = 0; nt < 4; nt++)
#pragma unroll
            for (int r = 0; r < 4; r++) acc[mt][nt][r] = 0.0f;

    auto issue_chunk = [&](int c, int buf) {
        const float* Asrc = (c < 4) ? feat : g_agg;
        const uint32_t* Bsrc = g_Wr + (c < 4 ? 0 : F * F);
        int kq = (c & 3) * 32;
#pragma unroll
        for (int l = 0; l < 4; l++) {
            int grow = r0 + a_row[l];
            int pb = (grow < n) ? 16 : 0;
            const float* g = &Asrc[(size_t)(grow < n ? grow : 0) * F + kq + a_q[l] * 4];
            cp16(sA_addr + (buf * SA_BUF + a_row[l] * SA_STRIDE + a_q[l] * 4) * 4, g, pb);
        }
#pragma unroll
        for (int l = 0; l < 4; l++) {
            const uint32_t* g = &Bsrc[(size_t)(kq + b_k[l]) * F + b_q[l] * 4];
            cp16(sB_addr + (buf * SB_BUF + b_k[l] * SB_STRIDE + b_q[l] * 4) * 4, g, 16);
        }
        asm volatile("cp.async.commit_group;" ::: "memory");
    };

    issue_chunk(0, 0);

    for (int c = 0; c < 8; c++) {
        int buf = c & 1;
        if (c < 7) {
            issue_chunk(c + 1, buf ^ 1);
            asm volatile("cp.async.wait_group 1;" ::: "memory");
        } else {
            asm volatile("cp.async.wait_group 0;" ::: "memory");
        }
        __syncthreads();

        const uint32_t* cA = &sA[buf * SA_BUF];
        const uint32_t* cB = &sB[buf * SB_BUF];
#pragma unroll
        for (int ks = 0; ks < 4; ks++) {
            int k8 = ks * 8;
            uint32_t a[4][4];
#pragma unroll
            for (int mt = 0; mt < 4; mt++) {
                int mrow = warp_m * 64 + mt * 16;
                a[mt][0] = cA[(mrow + qr    ) * SA_STRIDE + k8 + qc    ];
                a[mt][1] = cA[(mrow + qr + 8) * SA_STRIDE + k8 + qc    ];
                a[mt][2] = cA[(mrow + qr    ) * SA_STRIDE + k8 + qc + 4];
                a[mt][3] = cA[(mrow + qr + 8) * SA_STRIDE + k8 + qc + 4];
            }
            uint32_t b[4][2];
#pragma unroll
            for (int nt = 0; nt < 4; nt++) {
                int ncol = warp_n * 32 + nt * 8;
                b[nt][0] = cB[(k8 + qc    ) * SB_STRIDE + ncol + qr];
                b[nt][1] = cB[(k8 + qc + 4) * SB_STRIDE + ncol + qr];
            }
#pragma unroll
            for (int mt = 0; mt < 4; mt++)
#pragma unroll
                for (int nt = 0; nt < 4; nt++)
                    mma_tf32(acc[mt][nt], a[mt], b[nt]);
        }
        __syncthreads();
    }

#pragma unroll
    for (int mt = 0; mt < 4; mt++) {
        int row0 = r0 + warp_m * 64 + mt * 16 + qr;
#pragma unroll
        for (int nt = 0; nt < 4; nt++) {
            int col = warp_n * 32 + nt * 8 + qc * 2;
            float b0 = __ldg(&bias[col]);
            float b1 = __ldg(&bias[col + 1]);
            if (row0 < n) {
                float2 o = make_float2(acc[mt][nt][0] + b0, acc[mt][nt][1] + b1);
                *(float2*)&out[(size_t)row0 * F + col] = o;
            }
            if (row0 + 8 < n) {
                float2 o = make_float2(acc[mt][nt][2] + b0, acc[mt][nt][3] + b1);
                *(float2*)&out[(size_t)(row0 + 8) * F + col] = o;
            }
        }
    }
}

// ---------------------------------------------------------------------------
// Launch: single stream: prep -> bucket -> gather -> gemm
// ---------------------------------------------------------------------------
extern "C" void kernel_launch(void* const* d_in, const int* in_sizes, int n_in,
                              void* d_out, int out_size) {
    const float* feat = (const float*)d_in[0];
    const float* tkv  = (const float*)d_in[1];
    const int*   tki  = (const int*)  d_in[2];
    const int*   src  = (const int*)  d_in[3];
    const int*   dst  = (const int*)  d_in[4];
    const float* Ws   = (const float*)d_in[5];
    const float* bs   = (const float*)d_in[6];
    const float* Wn   = (const float*)d_in[7];
    float* out = (float*)d_out;

    const int n = N_NODES;
    const int e = E_EDGES;

    cudaFuncSetAttribute(gemm_mma_kernel,
                         cudaFuncAttributeMaxDynamicSharedMemorySize, SMEM_BYTES);

    prep_kernel<<<(n * 32 + 255) / 256, 256>>>(tkv, tki, Ws, Wn, n);
    bucket_kernel<<<(e / 4 + 255) / 256, 256>>>(src, dst, e / 4);
    gather_kernel<<<(n + 7) / 8, 256>>>(n);
    gemm_mma_kernel<<<(n + 127) / 128, 256, SMEM_BYTES>>>(feat, bs, out, n);
}